// round 7
// baseline (speedup 1.0000x reference)
#include <cuda_runtime.h>
#include <cuda_fp16.h>

// ---------------------------------------------------------------------------
// InterpolatingBSpline2d, round 6: SINGLE fused kernel.
//
// Every block computes the full spline-coefficient solve in its own smem
// (redundant across blocks; data is 64 KB and L2-resident), then runs the
// measured-27us gather loop. This removes the separate coef kernel, one
// graph launch, and the global-table round-trip (the unexplained 12.5us gap).
//
// Memory trick: unified in-place layout in one 69,696-B smem buffer.
//   U(c, jx, my) [fp32 cx/dp value] lives at float index
//     base_c + jx*132 + my*2 + (c&1),   base_c = (c>=2 ? 8712 : 0)
//   i.e. channels 0,1 live inside what becomes copy0's table rows, channels
//   2,3 inside copy1's rows. Final table halfs overwrite these floats during
//   back-substitution, always at offsets STRICTLY ABOVE every still-pending
//   dp read (>=2-float slack). The 4 channel lanes of one jx share a warp
//   (t = 4*jx + c) and use volatile smem ops so lockstep + program order
//   guarantee the cross-lane write-after-read discipline.
//
// Final table layout (identical to R5 gather):
//   copy0 half idx (x*66+y)*4+c ; copy1 = copy0 shifted one y (dual-copy).
// ---------------------------------------------------------------------------

#define M_GRID   64
#define NP2      66
#define NINNER   62
#define NCH      4
#define ROW_F    132                      // floats per (jx,copy) row = 528 B
#define COPY_HALFS (NP2 * NP2 * NCH)      // 17424 halfs = 34,848 B per copy
#define COPY_F   (COPY_HALFS / 2)         // 8712 floats per copy region
#define SMEM_BYTES (2 * COPY_HALFS * 2)   // 69,696

// ---- compile-time Thomas factors ------------------------------------------
struct Fac { float cp[NINNER]; float invden[NINNER]; };

constexpr Fac make_fac() {
    Fac f{};
    const float B = 2.0f / 3.0f, A = 1.0f / 6.0f;
    float c = A / B;
    f.cp[0] = c;
    f.invden[0] = 1.0f / B;
    for (int m = 1; m < NINNER; ++m) {
        float den = B - A * c;
        float inv = 1.0f / den;
        c = A * inv;
        f.cp[m] = c;
        f.invden[m] = inv;
    }
    return f;
}
__constant__ Fac FAC = make_fac();

__device__ __forceinline__ unsigned short f2h(float v)
{
    return __half_as_ushort(__float2half_rn(v));
}

__device__ __forceinline__ float2 h2f(unsigned v)
{
    __half2 h = *reinterpret_cast<const __half2*>(&v);
    return __half22float2(h);
}

__global__ void __launch_bounds__(512, 3) bspline_fused(
    const float* __restrict__ data,
    const float2* __restrict__ u,
    float4* __restrict__ out, int n)
{
    extern __shared__ __align__(16) float sf[];     // 69,696 B
    __half* sh = reinterpret_cast<__half*>(sf);
    const int t = threadIdx.x;
    const float S = 1.0f / 6.0f;

    // ======== stage 1: solve along x (64 threads, 4 my-chains each) ========
    if (t < 64) {
        int c = t >> 4, q = t & 15;                 // my = 4q..4q+3
        const float4* df = reinterpret_cast<const float4*>(data) + c * 1024 + q;
        volatile float* B = sf + ((c & 2) ? COPY_F : 0) + 8 * q + (c & 1);
        // slot (jx, my=4q+j) at B[jx*132 + 2*j]

        float4 v0 = df[0];
        float4 v  = df[16];
        float d0x = v0.x, d0y = v0.y, d0z = v0.z, d0w = v0.w;
        float ax = (v.x - d0x * S) * FAC.invden[0];
        float ay = (v.y - d0y * S) * FAC.invden[0];
        float az = (v.z - d0z * S) * FAC.invden[0];
        float aw = (v.w - d0w * S) * FAC.invden[0];
        B[0] = ax; B[2] = ay; B[4] = az; B[6] = aw;
#pragma unroll
        for (int m = 1; m <= 60; ++m) {
            v = df[(m + 1) * 16];
            ax = (v.x - ax * S) * FAC.invden[m];
            ay = (v.y - ay * S) * FAC.invden[m];
            az = (v.z - az * S) * FAC.invden[m];
            aw = (v.w - aw * S) * FAC.invden[m];
            B[m * ROW_F + 0] = ax; B[m * ROW_F + 2] = ay;
            B[m * ROW_F + 4] = az; B[m * ROW_F + 6] = aw;
        }
        float4 v62 = df[62 * 16], v63 = df[63 * 16];
        ax = (v62.x - v63.x * S - ax * S) * FAC.invden[61];
        ay = (v62.y - v63.y * S - ay * S) * FAC.invden[61];
        az = (v62.z - v63.z * S - az * S) * FAC.invden[61];
        aw = (v62.w - v63.w * S - aw * S) * FAC.invden[61];

        // back-substitution: outputs jx=0..65 (fp32), in place
        float zx = ax, zy = ay, zz = az, zw = aw;
        B[65 * ROW_F + 0] = 2.0f * v63.x - zx; B[65 * ROW_F + 2] = 2.0f * v63.y - zy;
        B[65 * ROW_F + 4] = 2.0f * v63.z - zz; B[65 * ROW_F + 6] = 2.0f * v63.w - zw;
        B[64 * ROW_F + 0] = v63.x; B[64 * ROW_F + 2] = v63.y;
        B[64 * ROW_F + 4] = v63.z; B[64 * ROW_F + 6] = v63.w;
        B[63 * ROW_F + 0] = zx; B[63 * ROW_F + 2] = zy;
        B[63 * ROW_F + 4] = zz; B[63 * ROW_F + 6] = zw;
#pragma unroll
        for (int m = 60; m >= 0; --m) {
            float px = B[m * ROW_F + 0], py = B[m * ROW_F + 2];
            float pz = B[m * ROW_F + 4], pw = B[m * ROW_F + 6];
            zx = px - FAC.cp[m] * zx;
            zy = py - FAC.cp[m] * zy;
            zz = pz - FAC.cp[m] * zz;
            zw = pw - FAC.cp[m] * zw;
            B[(m + 2) * ROW_F + 0] = zx; B[(m + 2) * ROW_F + 2] = zy;
            B[(m + 2) * ROW_F + 4] = zz; B[(m + 2) * ROW_F + 6] = zw;
        }
        B[ROW_F + 0] = d0x; B[ROW_F + 2] = d0y;
        B[ROW_F + 4] = d0z; B[ROW_F + 6] = d0w;
        B[0] = 2.0f * d0x - zx; B[2] = 2.0f * d0y - zy;
        B[4] = 2.0f * d0z - zz; B[6] = 2.0f * d0w - zw;
    }
    __syncthreads();

    // ======== stage 2: solve along y (264 threads, t = 4*jx + c) ========
    if (t < NCH * NP2) {
        int jx = t >> 2, c = t & 3;
        volatile float* R = sf + ((c & 2) ? COPY_F : 0) + jx * ROW_F + (c & 1);
        volatile unsigned short* T =
            reinterpret_cast<volatile unsigned short*>(sh);

        float d0 = R[0];
        float carry = (R[2] - d0 * S) * FAC.invden[0];
        R[0] = carry;                                 // dp[0]
#pragma unroll
        for (int m = 1; m <= 60; ++m) {
            carry = (R[(m + 1) * 2] - carry * S) * FAC.invden[m];
            R[m * 2] = carry;                         // dp[m]
        }
        float s62 = R[62 * 2], d63 = R[63 * 2];
        carry = (s62 - d63 * S - carry * S) * FAC.invden[61];   // dp[61]

        const int r0 = jx * 264 + c;                  // copy0 half base
        const int r1 = COPY_HALFS + jx * 264 + c;     // copy1 half base
        float z = carry;                              // x63
        unsigned short h;
        h = f2h(2.0f * d63 - z); T[r0 + 65 * 4] = h; T[r1 + 64 * 4] = h;
        h = f2h(d63);            T[r0 + 64 * 4] = h; T[r1 + 63 * 4] = h;
        h = f2h(z);              T[r0 + 63 * 4] = h; T[r1 + 62 * 4] = h;
#pragma unroll
        for (int m = 60; m >= 0; --m) {
            float dpm = R[m * 2];
            z = dpm - FAC.cp[m] * z;
            h = f2h(z);
            T[r0 + (m + 2) * 4] = h;                  // copy0 slot y=m+2
            T[r1 + (m + 1) * 4] = h;                  // copy1 slot y=m+1
        }
        h = f2h(d0); T[r0 + 4] = h; T[r1] = h;        // y=1 (copy1 y=0)
        T[r0] = f2h(2.0f * d0 - z);                   // y=0 (z holds x2)
    }
    __syncthreads();

    // ======== gather (identical to round-5 loop, 27.1us measured) ========
    int stride = gridDim.x * blockDim.x;
    for (int i = blockIdx.x * blockDim.x + t; i < n; i += stride) {
        float2 p = u[i];
        float uxn = p.x * 63.0f;
        float fx  = floorf(uxn);
        int   ix  = (int)fx;
        float tx  = uxn - fx;
        if (uxn < 0.0f)   { ix = 0;  tx = uxn; }
        if (uxn >= 62.0f) { ix = 62; tx = uxn - 62.0f; }

        float uyn = p.y * 63.0f;
        float fy  = floorf(uyn);
        int   iy  = (int)fy;
        float ty  = uyn - fy;
        if (uyn < 0.0f)   { iy = 0;  ty = uyn; }
        if (uyn >= 62.0f) { iy = 62; ty = uyn - 62.0f; }

        float wx0 = ((-S * tx + 0.5f) * tx - 0.5f) * tx + S;
        float wx1 = ((0.5f * tx - 1.0f) * tx) * tx + (2.0f / 3.0f);
        float wx2 = ((-0.5f * tx + 0.5f) * tx + 0.5f) * tx + S;
        float wx3 = (S * tx) * tx * tx;

        float wy0 = ((-S * ty + 0.5f) * ty - 0.5f) * ty + S;
        float wy1 = ((0.5f * ty - 1.0f) * ty) * ty + (2.0f / 3.0f);
        float wy2 = ((-0.5f * ty + 0.5f) * ty + 0.5f) * ty + S;
        float wy3 = (S * ty) * ty * ty;

        int iy2 = iy & ~1;
        const uint4* bp = reinterpret_cast<const uint4*>(
            sh + (iy & 1) * COPY_HALFS + (ix * NP2 + iy2) * NCH);

        float acc0 = 0.0f, acc1 = 0.0f, acc2 = 0.0f, acc3 = 0.0f;
#pragma unroll
        for (int dx = 0; dx < 4; ++dx) {
            uint4 qa = bp[dx * 33];        // y-taps 0,1 (each: c01, c23)
            uint4 qb = bp[dx * 33 + 1];    // y-taps 2,3
            float2 a01 = h2f(qa.x), a23 = h2f(qa.y);
            float2 b01 = h2f(qa.z), b23 = h2f(qa.w);
            float2 c01 = h2f(qb.x), c23 = h2f(qb.y);
            float2 d01 = h2f(qb.z), d23 = h2f(qb.w);

            float r0 = a01.x * wy0 + b01.x * wy1 + c01.x * wy2 + d01.x * wy3;
            float r1 = a01.y * wy0 + b01.y * wy1 + c01.y * wy2 + d01.y * wy3;
            float r2 = a23.x * wy0 + b23.x * wy1 + c23.x * wy2 + d23.x * wy3;
            float r3 = a23.y * wy0 + b23.y * wy1 + c23.y * wy2 + d23.y * wy3;

            float wx = (dx == 0) ? wx0 : (dx == 1) ? wx1 : (dx == 2) ? wx2 : wx3;
            acc0 += wx * r0;
            acc1 += wx * r1;
            acc2 += wx * r2;
            acc3 += wx * r3;
        }
        out[i] = make_float4(acc0, acc1, acc2, acc3);
    }
}

extern "C" void kernel_launch(void* const* d_in, const int* in_sizes, int n_in,
                              void* d_out, int out_size)
{
    const float2* u    = (const float2*)d_in[0];
    const float*  data = (const float*)d_in[1];
    int n = in_sizes[0] / 2;

    cudaFuncSetAttribute(bspline_fused,
                         cudaFuncAttributeMaxDynamicSharedMemorySize, SMEM_BYTES);

    bspline_fused<<<444, 512, SMEM_BYTES>>>(data, u, (float4*)d_out, n);
}

// round 8
// speedup vs baseline: 1.1689x; 1.1689x over previous
#include <cuda_runtime.h>
#include <cuda_fp16.h>

// ---------------------------------------------------------------------------
// InterpolatingBSpline2d, round 7: single fused kernel, de-serialized
// prologue, full-occupancy gather.
//
// R6 lesson: the all-volatile prologue serialized 62 dependent LDG/LDS
// iterations (~15us). Fix:
//   stage1: 256 threads, one (c,my) chain each, PLAIN memory ops (each
//           thread's float slots are exclusive; loads batch freely).
//   stage2: 264 threads (t=4*jx+c), plain loads + volatile HALF STORES of
//           copy0 ONLY. All remaining in-place clobbers have 2-iteration
//           slack within a lockstep warp (the slack-1 hazard came from the
//           copy1 stores, now removed).
//   copy1 = copy0 shifted one y-slot, built by a block-wide uint2 smem copy.
//
// Unified in-place smem layout (one 69,696B buffer):
//   fp32 slot U(c,jx,my) at float index (c&2 ? 8712 : 0) + jx*132 + 2*my + (c&1)
//   i.e. channels 0,1 live where copy0's fp16 rows will be, channels 2,3
//   where copy1's rows will be. Back-substitution overwrites floats with
//   halfs strictly above every still-pending read.
//
// Gather: fp16 dual shifted-copy table, 8x LDS.128/point (measured 27.1us at
// 70% occ in R5). Now 1024-thread blocks -> 2 blocks/SM -> 2048 thr/SM
// (100% occ); __launch_bounds__(1024,2) keeps regs at 32 (R5 gather = 32).
// ---------------------------------------------------------------------------

#define M_GRID   64
#define NP2      66
#define NINNER   62
#define NCH      4
#define ROW_F    132                      // floats per (jx, copy) row = 528 B
#define NSLOT    (NP2 * NP2)              // 4356 (x,y) slots per copy
#define COPY_HALFS (NSLOT * NCH)          // 17424 halfs = 34,848 B per copy
#define COPY_F   (COPY_HALFS / 2)         // 8712 floats per copy region
#define SMEM_BYTES (2 * COPY_HALFS * 2)   // 69,696

// ---- compile-time Thomas factors ------------------------------------------
struct Fac { float cp[NINNER]; float invden[NINNER]; };

constexpr Fac make_fac() {
    Fac f{};
    const float B = 2.0f / 3.0f, A = 1.0f / 6.0f;
    float c = A / B;
    f.cp[0] = c;
    f.invden[0] = 1.0f / B;
    for (int m = 1; m < NINNER; ++m) {
        float den = B - A * c;
        float inv = 1.0f / den;
        c = A * inv;
        f.cp[m] = c;
        f.invden[m] = inv;
    }
    return f;
}
__constant__ Fac FAC = make_fac();

__device__ __forceinline__ unsigned short f2h(float v)
{
    return __half_as_ushort(__float2half_rn(v));
}

__device__ __forceinline__ float2 h2f(unsigned v)
{
    __half2 h = *reinterpret_cast<const __half2*>(&v);
    return __half22float2(h);
}

__global__ void __launch_bounds__(1024, 2) bspline_fused(
    const float* __restrict__ data,
    const float2* __restrict__ u,
    float4* __restrict__ out, int n)
{
    extern __shared__ __align__(16) float sf[];     // 69,696 B
    __half* sh = reinterpret_cast<__half*>(sf);
    const int t = threadIdx.x;
    const float S = 1.0f / 6.0f;

    // ======== stage 1: solve along x (256 threads, one (c,my) chain) ========
    if (t < 256) {
        const int c  = t >> 6;
        const int my = t & 63;
        const float* src = data + c * (M_GRID * M_GRID) + my;   // stride 64
        float* B = sf + ((c & 2) ? COPY_F : 0) + 2 * my + (c & 1);
        // output/scratch slot jx at B[jx*132]

        float d0 = src[0];
        float a  = (src[64] - d0 * S) * FAC.invden[0];
        B[0] = a;                                   // dp[0]
#pragma unroll
        for (int m = 1; m <= 60; ++m) {
            a = (src[(m + 1) * 64] - a * S) * FAC.invden[m];
            B[m * ROW_F] = a;                       // dp[m]
        }
        float d63 = src[63 * 64];
        a = (src[62 * 64] - d63 * S - a * S) * FAC.invden[61];  // dp[61]

        float z = a;                                // x63
        B[65 * ROW_F] = 2.0f * d63 - z;
        B[64 * ROW_F] = d63;
        B[63 * ROW_F] = z;
#pragma unroll
        for (int m = 60; m >= 0; --m) {
            z = B[m * ROW_F] - FAC.cp[m] * z;       // read dp[m], emit x_{m+2}
            B[(m + 2) * ROW_F] = z;                 // slack-2, own-thread
        }
        B[ROW_F] = d0;                              // x1
        B[0]     = 2.0f * d0 - z;                   // x0 (z holds x2)
    }
    __syncthreads();

    // ======== stage 2: solve along y (264 threads, t = 4*jx + c) ========
    if (t < NCH * NP2) {
        const int jx = t >> 2, c = t & 3;
        const float* R = sf + ((c & 2) ? COPY_F : 0) + jx * ROW_F + (c & 1);
        float* W = const_cast<float*>(R);
        volatile unsigned short* T =
            reinterpret_cast<volatile unsigned short*>(sh);
        const int r0 = jx * (NP2 * NCH) + c;        // copy0 half base for row jx

        float d0 = R[0];
        float carry = (R[2] - d0 * S) * FAC.invden[0];
        W[0] = carry;                               // dp[0]
#pragma unroll
        for (int m = 1; m <= 60; ++m) {
            carry = (R[(m + 1) * 2] - carry * S) * FAC.invden[m];
            W[m * 2] = carry;                       // dp[m]
        }
        float s62 = R[62 * 2], d63 = R[63 * 2];
        carry = (s62 - d63 * S - carry * S) * FAC.invden[61];   // dp[61]

        float z = carry;                            // x63
        T[r0 + 65 * 4] = f2h(2.0f * d63 - z);       // y=65
        T[r0 + 64 * 4] = f2h(d63);                  // y=64
        T[r0 + 63 * 4] = f2h(z);                    // y=63
#pragma unroll
        for (int m = 60; m >= 0; --m) {
            z = R[m * 2] - FAC.cp[m] * z;           // plain load (hoist-safe)
            T[r0 + (m + 2) * 4] = f2h(z);           // clobbers dp[m+2]: slack 2
        }
        T[r0 + 4] = f2h(d0);                        // y=1
        T[r0]     = f2h(2.0f * d0 - z);             // y=0 (z holds x2)
    }
    __syncthreads();

    // ======== copy1 = copy0 shifted one y-slot (8B granules) ========
    {
        uint2* s64 = reinterpret_cast<uint2*>(sf);
        for (int j = t; j < NSLOT - 1; j += blockDim.x)
            s64[NSLOT + j] = s64[j + 1];
    }
    __syncthreads();

    // ======== gather (R5 loop, measured 27.1us @70% occ) ========
    int stride = gridDim.x * blockDim.x;
    for (int i = blockIdx.x * blockDim.x + t; i < n; i += stride) {
        float2 p = u[i];
        float uxn = p.x * 63.0f;
        float fx  = floorf(uxn);
        int   ix  = (int)fx;
        float tx  = uxn - fx;
        if (uxn < 0.0f)   { ix = 0;  tx = uxn; }
        if (uxn >= 62.0f) { ix = 62; tx = uxn - 62.0f; }

        float uyn = p.y * 63.0f;
        float fy  = floorf(uyn);
        int   iy  = (int)fy;
        float ty  = uyn - fy;
        if (uyn < 0.0f)   { iy = 0;  ty = uyn; }
        if (uyn >= 62.0f) { iy = 62; ty = uyn - 62.0f; }

        float wx0 = ((-S * tx + 0.5f) * tx - 0.5f) * tx + S;
        float wx1 = ((0.5f * tx - 1.0f) * tx) * tx + (2.0f / 3.0f);
        float wx2 = ((-0.5f * tx + 0.5f) * tx + 0.5f) * tx + S;
        float wx3 = (S * tx) * tx * tx;

        float wy0 = ((-S * ty + 0.5f) * ty - 0.5f) * ty + S;
        float wy1 = ((0.5f * ty - 1.0f) * ty) * ty + (2.0f / 3.0f);
        float wy2 = ((-0.5f * ty + 0.5f) * ty + 0.5f) * ty + S;
        float wy3 = (S * ty) * ty * ty;

        int iy2 = iy & ~1;
        const uint4* bp = reinterpret_cast<const uint4*>(
            sh + (iy & 1) * COPY_HALFS + (ix * NP2 + iy2) * NCH);

        float acc0 = 0.0f, acc1 = 0.0f, acc2 = 0.0f, acc3 = 0.0f;
#pragma unroll
        for (int dx = 0; dx < 4; ++dx) {
            uint4 qa = bp[dx * 33];        // y-taps 0,1 (each: c01, c23)
            uint4 qb = bp[dx * 33 + 1];    // y-taps 2,3
            float2 a01 = h2f(qa.x), a23 = h2f(qa.y);
            float2 b01 = h2f(qa.z), b23 = h2f(qa.w);
            float2 c01 = h2f(qb.x), c23 = h2f(qb.y);
            float2 d01 = h2f(qb.z), d23 = h2f(qb.w);

            float r0 = a01.x * wy0 + b01.x * wy1 + c01.x * wy2 + d01.x * wy3;
            float r1 = a01.y * wy0 + b01.y * wy1 + c01.y * wy2 + d01.y * wy3;
            float r2 = a23.x * wy0 + b23.x * wy1 + c23.x * wy2 + d23.x * wy3;
            float r3 = a23.y * wy0 + b23.y * wy1 + c23.y * wy2 + d23.y * wy3;

            float wx = (dx == 0) ? wx0 : (dx == 1) ? wx1 : (dx == 2) ? wx2 : wx3;
            acc0 += wx * r0;
            acc1 += wx * r1;
            acc2 += wx * r2;
            acc3 += wx * r3;
        }
        out[i] = make_float4(acc0, acc1, acc2, acc3);
    }
}

extern "C" void kernel_launch(void* const* d_in, const int* in_sizes, int n_in,
                              void* d_out, int out_size)
{
    const float2* u    = (const float2*)d_in[0];
    const float*  data = (const float*)d_in[1];
    int n = in_sizes[0] / 2;

    cudaFuncSetAttribute(bspline_fused,
                         cudaFuncAttributeMaxDynamicSharedMemorySize, SMEM_BYTES);

    bspline_fused<<<296, 1024, SMEM_BYTES>>>(data, u, (float4*)d_out, n);
}